// round 2
// baseline (speedup 1.0000x reference)
#include <cuda_runtime.h>
#include <cuda_fp16.h>
#include <cstdint>

// ============================================================================
// Problem dims
// ============================================================================
constexpr int D_MODEL = 1024;
constexpr int BATCH   = 4;
constexpr int SEQ     = 4096;
constexpr int M       = BATCH * SEQ;   // 16384 rows (B*T)
constexpr int K       = D_MODEL;       // 1024
constexpr int N2      = 2 * D_MODEL;   // 2048 (z | h halves)

// Scan chunking
constexpr int TC    = 128;             // timesteps per chunk
constexpr int NCH   = SEQ / TC;        // 32 chunks
constexpr int NCHAN = BATCH * D_MODEL; // 4096 channels

// ============================================================================
// Scratch (device globals — no allocation allowed)
// ============================================================================
__device__ __align__(16) __half g_A[(size_t)M * K];    // x fp16   (32 MB)
__device__ __align__(16) __half g_B[(size_t)N2 * K];   // W^T fp16 ( 4 MB)
__device__ __align__(16) float  g_pre[(size_t)M * N2]; // pre-acts (128 MB)
__device__ float g_cA[NCH * NCHAN];
__device__ float g_cB[NCH * NCHAN];
__device__ float g_carry[NCH * NCHAN];

// ============================================================================
// PTX helpers (sm_100 base-target safe: cp.async / ldmatrix / mma.sync only)
// ============================================================================
__device__ __forceinline__ uint32_t smem_u32(const void* p) {
    uint32_t a;
    asm("{ .reg .u64 t; cvta.to.shared.u64 t, %1; cvt.u32.u64 %0, t; }" : "=r"(a) : "l"(p));
    return a;
}
__device__ __forceinline__ void cp_async16(uint32_t s, const void* g) {
    asm volatile("cp.async.cg.shared.global [%0], [%1], 16;" :: "r"(s), "l"(g) : "memory");
}
#define CP_COMMIT() asm volatile("cp.async.commit_group;" ::: "memory")
template <int N>
__device__ __forceinline__ void cp_wait() {
    asm volatile("cp.async.wait_group %0;" :: "n"(N) : "memory");
}
__device__ __forceinline__ void ldsm_x4(uint32_t& r0, uint32_t& r1, uint32_t& r2, uint32_t& r3,
                                        uint32_t s) {
    asm volatile("ldmatrix.sync.aligned.m8n8.x4.shared.b16 {%0,%1,%2,%3}, [%4];"
                 : "=r"(r0), "=r"(r1), "=r"(r2), "=r"(r3) : "r"(s));
}
__device__ __forceinline__ void mma16816(float* c, const uint32_t* a, const uint32_t* b) {
    asm volatile(
        "mma.sync.aligned.m16n8k16.row.col.f32.f16.f16.f32 "
        "{%0,%1,%2,%3}, {%4,%5,%6,%7}, {%8,%9}, {%0,%1,%2,%3};"
        : "+f"(c[0]), "+f"(c[1]), "+f"(c[2]), "+f"(c[3])
        : "r"(a[0]), "r"(a[1]), "r"(a[2]), "r"(a[3]), "r"(b[0]), "r"(b[1]));
}
#define SWZ128(off) ((off) ^ (((off) >> 3) & 0x70))

// ============================================================================
// Kernel 1: x (fp32) -> fp16
// ============================================================================
__global__ void k_convert_x(const float4* __restrict__ x4) {
    int i = blockIdx.x * blockDim.x + threadIdx.x;   // one float4 per thread
    if (i >= (M * K) / 4) return;
    float4 v = x4[i];
    __half2 h0 = __floats2half2_rn(v.x, v.y);
    __half2 h1 = __floats2half2_rn(v.z, v.w);
    uint2 p;
    p.x = *reinterpret_cast<uint32_t*>(&h0);
    p.y = *reinterpret_cast<uint32_t*>(&h1);
    reinterpret_cast<uint2*>(g_A)[i] = p;
}

// ============================================================================
// Kernel 2: W [K,N] fp32 -> B [N,K] fp16 (transposed, N-major rows)
// rowoff = 0 for Wz, 1024 for Wh
// ============================================================================
__global__ void k_convert_w(const float* __restrict__ W, int rowoff) {
    __shared__ float t[32][33];
    int tx = threadIdx.x, ty = threadIdx.y;
    int K0 = blockIdx.x * 32, N0 = blockIdx.y * 32;
    t[ty][tx] = W[(size_t)(K0 + ty) * D_MODEL + (N0 + tx)];
    __syncthreads();
    int n = N0 + ty, k = K0 + tx;
    g_B[(size_t)(rowoff + n) * K + k] = __float2half_rn(t[tx][ty]);
}

// ============================================================================
// Kernel 3: GEMM  pre[M, N2] = A @ B^T + bias   (fp16 HMMA, fp32 accum)
// BM=128, BN=256, BK=64, 512 threads, 2-stage cp.async pipeline
// ============================================================================
constexpr int BM = 128, BN = 256, BK = 64;
constexpr int KT = K / BK;                 // 16 k-chunks
constexpr int SA_BYTES = BM * 128;         // 16 KB  (128 rows x 128B)
constexpr int SB_BYTES = BN * 128;         // 32 KB
constexpr int STAGE    = SA_BYTES + SB_BYTES;   // 48 KB
constexpr int SMEM_TOTAL = 2 * STAGE;           // 96 KB

__global__ void __launch_bounds__(512, 1)
k_gemm(const float* __restrict__ bz, const float* __restrict__ bh) {
    extern __shared__ char smem[];
    uint32_t sbase = smem_u32(smem);
    int tid = threadIdx.x;
    int wid = tid >> 5, lid = tid & 31;
    int n0 = blockIdx.x * BN;   // 0..2048 step 256
    int m0 = blockIdx.y * BM;   // 0..16384 step 128
    int wm = wid & 1;           // 2 warp-rows (64 rows each)
    int wn = wid >> 1;          // 8 warp-cols (32 cols each)

    const char* gA = (const char*)g_A + (size_t)m0 * (K * 2);
    const char* gB = (const char*)g_B + (size_t)n0 * (K * 2);

    // per-thread load coords (16B chunks; row-major [rows][8 chunks])
    int la_row[2], la_col[2];
    uint32_t la_s[2];
    #pragma unroll
    for (int i = 0; i < 2; i++) {
        int idx = tid + i * 512;
        la_row[i] = idx >> 3; la_col[i] = (idx & 7) * 16;
        la_s[i] = SWZ128((uint32_t)(la_row[i] * 128 + la_col[i]));
    }
    int lb_row[4], lb_col[4];
    uint32_t lb_s[4];
    #pragma unroll
    for (int i = 0; i < 4; i++) {
        int idx = tid + i * 512;
        lb_row[i] = idx >> 3; lb_col[i] = (idx & 7) * 16;
        lb_s[i] = SWZ128((uint32_t)(lb_row[i] * 128 + lb_col[i]));
    }

    auto load_stage = [&](int kt, int buf) {
        uint32_t sA = sbase + buf * STAGE;
        uint32_t sB = sA + SA_BYTES;
        size_t kb = (size_t)kt * (BK * 2);   // 128 bytes per row chunk
        #pragma unroll
        for (int i = 0; i < 2; i++)
            cp_async16(sA + la_s[i], gA + (size_t)la_row[i] * (K * 2) + kb + la_col[i]);
        #pragma unroll
        for (int i = 0; i < 4; i++)
            cp_async16(sB + lb_s[i], gB + (size_t)lb_row[i] * (K * 2) + kb + lb_col[i]);
        CP_COMMIT();
    };

    float acc[4][4][4];
    #pragma unroll
    for (int i = 0; i < 4; i++)
        #pragma unroll
        for (int j = 0; j < 4; j++)
            #pragma unroll
            for (int r = 0; r < 4; r++) acc[i][j][r] = 0.0f;

    // ldmatrix lane geometry
    int mat = lid >> 3, r8 = lid & 7;
    // A: row = wm*64 + mf*16 + (mat&1)*8 + r8 ; col = ks*32 + (mat>>1)*16
    int a_row_base = wm * 64 + (mat & 1) * 8 + r8;
    int a_col_base = (mat >> 1) * 16;
    // B: row = wn*32 + np*16 + (mat>>1)*8 + r8 ; col = ks*32 + (mat&1)*16
    int b_row_base = wn * 32 + (mat >> 1) * 8 + r8;
    int b_col_base = (mat & 1) * 16;

    load_stage(0, 0);

    for (int kt = 0; kt < KT; kt++) {
        if (kt + 1 < KT) load_stage(kt + 1, (kt + 1) & 1);
        if (kt + 1 < KT) cp_wait<1>(); else cp_wait<0>();
        __syncthreads();

        uint32_t sA = sbase + (kt & 1) * STAGE;
        uint32_t sB = sA + SA_BYTES;

        #pragma unroll
        for (int ks = 0; ks < 4; ks++) {
            uint32_t a[4][4], b[4][2];
            #pragma unroll
            for (int mf = 0; mf < 4; mf++) {
                uint32_t off = SWZ128((uint32_t)((a_row_base + mf * 16) * 128 +
                                                 ks * 32 + a_col_base));
                ldsm_x4(a[mf][0], a[mf][1], a[mf][2], a[mf][3], sA + off);
            }
            #pragma unroll
            for (int np = 0; np < 2; np++) {
                uint32_t off = SWZ128((uint32_t)((b_row_base + np * 16) * 128 +
                                                 ks * 32 + b_col_base));
                uint32_t r0, r1, r2, r3;
                ldsm_x4(r0, r1, r2, r3, sB + off);
                b[np * 2 + 0][0] = r0; b[np * 2 + 0][1] = r1;
                b[np * 2 + 1][0] = r2; b[np * 2 + 1][1] = r3;
            }
            #pragma unroll
            for (int mf = 0; mf < 4; mf++)
                #pragma unroll
                for (int nf = 0; nf < 4; nf++)
                    mma16816(acc[mf][nf], a[mf], b[nf]);
        }
        __syncthreads();
    }

    // Epilogue: add bias, write fp32 pre-activations
    const float* bias = (n0 < D_MODEL) ? (bz + n0) : (bh + n0 - D_MODEL);
    int lr = lid >> 2, lc = (lid & 3) * 2;
    #pragma unroll
    for (int mf = 0; mf < 4; mf++) {
        int row0 = m0 + wm * 64 + mf * 16 + lr;
        #pragma unroll
        for (int nf = 0; nf < 4; nf++) {
            int col = wn * 32 + nf * 8 + lc;
            float bx = __ldg(bias + col), by = __ldg(bias + col + 1);
            float2 v0 = {acc[mf][nf][0] + bx, acc[mf][nf][1] + by};
            float2 v1 = {acc[mf][nf][2] + bx, acc[mf][nf][3] + by};
            *(float2*)(g_pre + (size_t)row0 * N2 + n0 + col)       = v0;
            *(float2*)(g_pre + (size_t)(row0 + 8) * N2 + n0 + col) = v1;
        }
    }
}

// ============================================================================
// Scan: h_t = (1-s)*h_{t-1} + s*h_tilde,  s = sigmoid(pre_z)
// ============================================================================
__device__ __forceinline__ float sigmoidf_(float z) {
    return 1.0f / (1.0f + __expf(-z));
}

__global__ void k_scan1() {
    int ch = blockIdx.x * blockDim.x + threadIdx.x;   // channel 0..4095
    int chunk = blockIdx.y;
    int b = ch >> 10, d = ch & (D_MODEL - 1);
    size_t row = (size_t)b * SEQ + (size_t)chunk * TC;
    const float* p = g_pre + row * N2 + d;
    float A = 1.0f, Bc = 0.0f;
    #pragma unroll 4
    for (int t = 0; t < TC; t++) {
        float z  = p[0];
        float ht = p[D_MODEL];
        p += N2;
        float s = sigmoidf_(z);
        float a = 1.0f - s;
        A *= a;
        Bc = __fmaf_rn(a, Bc, s * ht);
    }
    g_cA[chunk * NCHAN + ch] = A;
    g_cB[chunk * NCHAN + ch] = Bc;
}

__global__ void k_scan2() {
    int ch = blockIdx.x * blockDim.x + threadIdx.x;
    float h = 0.0f;
    #pragma unroll
    for (int c = 0; c < NCH; c++) {
        g_carry[c * NCHAN + ch] = h;
        h = __fmaf_rn(g_cA[c * NCHAN + ch], h, g_cB[c * NCHAN + ch]);
    }
}

__global__ void k_scan3(float* __restrict__ out) {
    int ch = blockIdx.x * blockDim.x + threadIdx.x;
    int chunk = blockIdx.y;
    int b = ch >> 10, d = ch & (D_MODEL - 1);
    size_t row = (size_t)b * SEQ + (size_t)chunk * TC;
    const float* p = g_pre + row * N2 + d;
    float* o = out + row * D_MODEL + d;
    float h = g_carry[chunk * NCHAN + ch];
    #pragma unroll 4
    for (int t = 0; t < TC; t++) {
        float z  = p[0];
        float ht = p[D_MODEL];
        p += N2;
        float s = sigmoidf_(z);
        h = __fmaf_rn(1.0f - s, h, s * ht);
        *o = h;
        o += D_MODEL;
    }
}

// ============================================================================
// Launch
// ============================================================================
extern "C" void kernel_launch(void* const* d_in, const int* in_sizes, int n_in,
                              void* d_out, int out_size) {
    const float* x  = (const float*)d_in[0];
    const float* Wz = (const float*)d_in[1];
    const float* bz = (const float*)d_in[2];
    const float* Wh = (const float*)d_in[3];
    const float* bh = (const float*)d_in[4];
    float* out = (float*)d_out;

    cudaFuncSetAttribute(k_gemm, cudaFuncAttributeMaxDynamicSharedMemorySize, SMEM_TOTAL);

    // 1. converts
    k_convert_x<<<(M * K / 4 + 255) / 256, 256>>>((const float4*)x);
    k_convert_w<<<dim3(32, 32), dim3(32, 32)>>>(Wz, 0);
    k_convert_w<<<dim3(32, 32), dim3(32, 32)>>>(Wh, D_MODEL);

    // 2. fused dual GEMM (fp16 mma.sync, fp32 accumulate)
    k_gemm<<<dim3(N2 / BN, M / BM), 512, SMEM_TOTAL>>>(bz, bh);

    // 3. chunked scan
    k_scan1<<<dim3(NCHAN / 256, NCH), 256>>>();
    k_scan2<<<NCHAN / 256, 256>>>();
    k_scan3<<<dim3(NCHAN / 256, NCH), 256>>>(out);
}

// round 3
// speedup vs baseline: 1.1248x; 1.1248x over previous
#include <cuda_runtime.h>
#include <cuda_fp16.h>
#include <cstdint>

// ============================================================================
// Problem dims
// ============================================================================
constexpr int D_MODEL = 1024;
constexpr int BATCH   = 4;
constexpr int SEQ     = 4096;
constexpr int M       = BATCH * SEQ;   // 16384 rows (B*T)
constexpr int K       = D_MODEL;       // 1024
constexpr int N2      = 2 * D_MODEL;   // 2048 (z | h halves)

// Scan chunking
constexpr int TC    = 128;             // timesteps per chunk
constexpr int NCH   = SEQ / TC;        // 32 chunks
constexpr int NCHAN = BATCH * D_MODEL; // 4096 channels

// ============================================================================
// Scratch (device globals — no allocation allowed)
// ============================================================================
__device__ __align__(16) __half g_A[(size_t)M * K];    // x fp16   (32 MB)
__device__ __align__(16) __half g_B[(size_t)N2 * K];   // W^T fp16 ( 4 MB)
__device__ __align__(16) float  g_pre[(size_t)M * N2]; // pre-acts (128 MB)
__device__ __align__(16) float  g_s[(size_t)M * D_MODEL]; // sigmoid(z) (64 MB)
__device__ float g_cA[NCH * NCHAN];
__device__ float g_cB[NCH * NCHAN];
__device__ float g_carry[NCH * NCHAN];

// ============================================================================
// PTX helpers (sm_100 base-target safe: cp.async / ldmatrix / mma.sync only)
// ============================================================================
__device__ __forceinline__ uint32_t smem_u32(const void* p) {
    uint32_t a;
    asm("{ .reg .u64 t; cvta.to.shared.u64 t, %1; cvt.u32.u64 %0, t; }" : "=r"(a) : "l"(p));
    return a;
}
__device__ __forceinline__ void cp_async16(uint32_t s, const void* g) {
    asm volatile("cp.async.cg.shared.global [%0], [%1], 16;" :: "r"(s), "l"(g) : "memory");
}
#define CP_COMMIT() asm volatile("cp.async.commit_group;" ::: "memory")
template <int N>
__device__ __forceinline__ void cp_wait() {
    asm volatile("cp.async.wait_group %0;" :: "n"(N) : "memory");
}
__device__ __forceinline__ void ldsm_x4(uint32_t& r0, uint32_t& r1, uint32_t& r2, uint32_t& r3,
                                        uint32_t s) {
    asm volatile("ldmatrix.sync.aligned.m8n8.x4.shared.b16 {%0,%1,%2,%3}, [%4];"
                 : "=r"(r0), "=r"(r1), "=r"(r2), "=r"(r3) : "r"(s));
}
__device__ __forceinline__ void mma16816(float* c, const uint32_t* a, const uint32_t* b) {
    asm volatile(
        "mma.sync.aligned.m16n8k16.row.col.f32.f16.f16.f32 "
        "{%0,%1,%2,%3}, {%4,%5,%6,%7}, {%8,%9}, {%0,%1,%2,%3};"
        : "+f"(c[0]), "+f"(c[1]), "+f"(c[2]), "+f"(c[3])
        : "r"(a[0]), "r"(a[1]), "r"(a[2]), "r"(a[3]), "r"(b[0]), "r"(b[1]));
}
#define SWZ128(off) ((off) ^ (((off) >> 3) & 0x70))

// sigmoid(z) = 0.5 + 0.5*tanh(z/2)  — single MUFU (tanh.approx, sm_75+)
__device__ __forceinline__ float sigmoid_fast(float z) {
    float t;
    asm("tanh.approx.f32 %0, %1;" : "=f"(t) : "f"(0.5f * z));
    return __fmaf_rn(0.5f, t, 0.5f);
}

// ============================================================================
// Kernel 1: x (fp32) -> fp16
// ============================================================================
__global__ void k_convert_x(const float4* __restrict__ x4) {
    int i = blockIdx.x * blockDim.x + threadIdx.x;   // one float4 per thread
    if (i >= (M * K) / 4) return;
    float4 v = x4[i];
    __half2 h0 = __floats2half2_rn(v.x, v.y);
    __half2 h1 = __floats2half2_rn(v.z, v.w);
    uint2 p;
    p.x = *reinterpret_cast<uint32_t*>(&h0);
    p.y = *reinterpret_cast<uint32_t*>(&h1);
    reinterpret_cast<uint2*>(g_A)[i] = p;
}

// ============================================================================
// Kernel 2: W [K,N] fp32 -> B [N,K] fp16 (transposed, N-major rows)
// rowoff = 0 for Wz, 1024 for Wh
// ============================================================================
__global__ void k_convert_w(const float* __restrict__ W, int rowoff) {
    __shared__ float t[32][33];
    int tx = threadIdx.x, ty = threadIdx.y;
    int K0 = blockIdx.x * 32, N0 = blockIdx.y * 32;
    t[ty][tx] = W[(size_t)(K0 + ty) * D_MODEL + (N0 + tx)];
    __syncthreads();
    int n = N0 + ty, k = K0 + tx;
    g_B[(size_t)(rowoff + n) * K + k] = __float2half_rn(t[tx][ty]);
}

// ============================================================================
// Kernel 3: GEMM  pre[M, N2] = A @ B^T + bias   (fp16 HMMA, fp32 accum)
// BM=128, BN=256, BK=64, 512 threads, 3-stage cp.async pipeline
// ============================================================================
constexpr int BM = 128, BN = 256, BK = 64;
constexpr int KT = K / BK;                 // 16 k-chunks
constexpr int SA_BYTES = BM * 128;         // 16 KB  (128 rows x 128B)
constexpr int SB_BYTES = BN * 128;         // 32 KB
constexpr int STAGE    = SA_BYTES + SB_BYTES;   // 48 KB
constexpr int NSTAGE   = 3;
constexpr int SMEM_TOTAL = NSTAGE * STAGE;      // 144 KB

__global__ void __launch_bounds__(512, 1)
k_gemm(const float* __restrict__ bz, const float* __restrict__ bh) {
    extern __shared__ char smem[];
    uint32_t sbase = smem_u32(smem);
    int tid = threadIdx.x;
    int wid = tid >> 5, lid = tid & 31;
    int n0 = blockIdx.x * BN;   // 0..2048 step 256
    int m0 = blockIdx.y * BM;   // 0..16384 step 128
    int wm = wid & 1;           // 2 warp-rows (64 rows each)
    int wn = wid >> 1;          // 8 warp-cols (32 cols each)

    const char* gA = (const char*)g_A + (size_t)m0 * (K * 2);
    const char* gB = (const char*)g_B + (size_t)n0 * (K * 2);

    // per-thread load coords (16B chunks; row-major [rows][8 chunks])
    int la_row[2], la_col[2];
    uint32_t la_s[2];
    #pragma unroll
    for (int i = 0; i < 2; i++) {
        int idx = tid + i * 512;
        la_row[i] = idx >> 3; la_col[i] = (idx & 7) * 16;
        la_s[i] = SWZ128((uint32_t)(la_row[i] * 128 + la_col[i]));
    }
    int lb_row[4], lb_col[4];
    uint32_t lb_s[4];
    #pragma unroll
    for (int i = 0; i < 4; i++) {
        int idx = tid + i * 512;
        lb_row[i] = idx >> 3; lb_col[i] = (idx & 7) * 16;
        lb_s[i] = SWZ128((uint32_t)(lb_row[i] * 128 + lb_col[i]));
    }

    auto load_stage = [&](int kt, int buf) {
        uint32_t sA = sbase + buf * STAGE;
        uint32_t sB = sA + SA_BYTES;
        size_t kb = (size_t)kt * (BK * 2);   // 128 bytes per row chunk
        #pragma unroll
        for (int i = 0; i < 2; i++)
            cp_async16(sA + la_s[i], gA + (size_t)la_row[i] * (K * 2) + kb + la_col[i]);
        #pragma unroll
        for (int i = 0; i < 4; i++)
            cp_async16(sB + lb_s[i], gB + (size_t)lb_row[i] * (K * 2) + kb + lb_col[i]);
        CP_COMMIT();
    };

    float acc[4][4][4];
    #pragma unroll
    for (int i = 0; i < 4; i++)
        #pragma unroll
        for (int j = 0; j < 4; j++)
            #pragma unroll
            for (int r = 0; r < 4; r++) acc[i][j][r] = 0.0f;

    // ldmatrix lane geometry
    int mat = lid >> 3, r8 = lid & 7;
    int a_row_base = wm * 64 + (mat & 1) * 8 + r8;
    int a_col_base = (mat >> 1) * 16;
    int b_row_base = wn * 32 + (mat >> 1) * 8 + r8;
    int b_col_base = (mat & 1) * 16;

    // prologue: prefetch 2 stages
    load_stage(0, 0);
    load_stage(1, 1);

    int buf = 0;                 // stage holding chunk kt
    int nbuf = 2;                // stage to fill next (chunk kt+2)
    for (int kt = 0; kt < KT; kt++) {
        if (kt == KT - 1) cp_wait<0>(); else cp_wait<1>();
        __syncthreads();                       // stage kt ready; stage nbuf free
        if (kt + 2 < KT) load_stage(kt + 2, nbuf);

        uint32_t sA = sbase + buf * STAGE;
        uint32_t sB = sA + SA_BYTES;

        #pragma unroll
        for (int ks = 0; ks < 4; ks++) {
            uint32_t a[4][4], b[4][2];
            #pragma unroll
            for (int mf = 0; mf < 4; mf++) {
                uint32_t off = SWZ128((uint32_t)((a_row_base + mf * 16) * 128 +
                                                 ks * 32 + a_col_base));
                ldsm_x4(a[mf][0], a[mf][1], a[mf][2], a[mf][3], sA + off);
            }
            #pragma unroll
            for (int np = 0; np < 2; np++) {
                uint32_t off = SWZ128((uint32_t)((b_row_base + np * 16) * 128 +
                                                 ks * 32 + b_col_base));
                uint32_t r0, r1, r2, r3;
                ldsm_x4(r0, r1, r2, r3, sB + off);
                b[np * 2 + 0][0] = r0; b[np * 2 + 0][1] = r1;
                b[np * 2 + 1][0] = r2; b[np * 2 + 1][1] = r3;
            }
            #pragma unroll
            for (int mf = 0; mf < 4; mf++)
                #pragma unroll
                for (int nf = 0; nf < 4; nf++)
                    mma16816(acc[mf][nf], a[mf], b[nf]);
        }
        buf = (buf == NSTAGE - 1) ? 0 : buf + 1;
        nbuf = (nbuf == NSTAGE - 1) ? 0 : nbuf + 1;
    }

    // Epilogue: add bias, write fp32 pre-activations
    const float* bias = (n0 < D_MODEL) ? (bz + n0) : (bh + n0 - D_MODEL);
    int lr = lid >> 2, lc = (lid & 3) * 2;
    #pragma unroll
    for (int mf = 0; mf < 4; mf++) {
        int row0 = m0 + wm * 64 + mf * 16 + lr;
        #pragma unroll
        for (int nf = 0; nf < 4; nf++) {
            int col = wn * 32 + nf * 8 + lc;
            float bx = __ldg(bias + col), by = __ldg(bias + col + 1);
            float2 v0 = {acc[mf][nf][0] + bx, acc[mf][nf][1] + by};
            float2 v1 = {acc[mf][nf][2] + bx, acc[mf][nf][3] + by};
            *(float2*)(g_pre + (size_t)row0 * N2 + n0 + col)       = v0;
            *(float2*)(g_pre + (size_t)(row0 + 8) * N2 + n0 + col) = v1;
        }
    }
}

// ============================================================================
// Scan: h_t = (1-s)*h_{t-1} + s*h_tilde,  s = sigmoid(pre_z)
// scan1 computes s ONCE (1 MUFU via tanh.approx), stores it; scan3 is FMA-only.
// ============================================================================
__global__ void k_scan1() {
    int ch = blockIdx.x * blockDim.x + threadIdx.x;   // channel 0..4095
    int chunk = blockIdx.y;
    int b = ch >> 10, d = ch & (D_MODEL - 1);
    size_t row = (size_t)b * SEQ + (size_t)chunk * TC;
    const float* p = g_pre + row * N2 + d;
    float* sp = g_s + row * D_MODEL + d;
    float A = 1.0f, Bc = 0.0f;
    #pragma unroll 4
    for (int t = 0; t < TC; t++) {
        float z  = p[0];
        float ht = p[D_MODEL];
        p += N2;
        float s = sigmoid_fast(z);
        *sp = s;
        sp += D_MODEL;
        float a = 1.0f - s;
        A *= a;
        Bc = __fmaf_rn(a, Bc, s * ht);
    }
    g_cA[chunk * NCHAN + ch] = A;
    g_cB[chunk * NCHAN + ch] = Bc;
}

__global__ void k_scan2() {
    int ch = blockIdx.x * blockDim.x + threadIdx.x;
    float h = 0.0f;
    #pragma unroll
    for (int c = 0; c < NCH; c++) {
        g_carry[c * NCHAN + ch] = h;
        h = __fmaf_rn(g_cA[c * NCHAN + ch], h, g_cB[c * NCHAN + ch]);
    }
}

__global__ void k_scan3(float* __restrict__ out) {
    int ch = blockIdx.x * blockDim.x + threadIdx.x;
    int chunk = blockIdx.y;
    int b = ch >> 10, d = ch & (D_MODEL - 1);
    size_t row = (size_t)b * SEQ + (size_t)chunk * TC;
    const float* ph = g_pre + row * N2 + D_MODEL + d;   // h-tilde half
    const float* sp = g_s + row * D_MODEL + d;
    float* o = out + row * D_MODEL + d;
    float h = g_carry[chunk * NCHAN + ch];
    #pragma unroll 4
    for (int t = 0; t < TC; t++) {
        float s  = sp[0];
        float ht = ph[0];
        sp += D_MODEL;
        ph += N2;
        h = __fmaf_rn(1.0f - s, h, s * ht);
        *o = h;
        o += D_MODEL;
    }
}

// ============================================================================
// Launch
// ============================================================================
extern "C" void kernel_launch(void* const* d_in, const int* in_sizes, int n_in,
                              void* d_out, int out_size) {
    const float* x  = (const float*)d_in[0];
    const float* Wz = (const float*)d_in[1];
    const float* bz = (const float*)d_in[2];
    const float* Wh = (const float*)d_in[3];
    const float* bh = (const float*)d_in[4];
    float* out = (float*)d_out;

    cudaFuncSetAttribute(k_gemm, cudaFuncAttributeMaxDynamicSharedMemorySize, SMEM_TOTAL);

    // 1. converts
    k_convert_x<<<(M * K / 4 + 255) / 256, 256>>>((const float4*)x);
    k_convert_w<<<dim3(32, 32), dim3(32, 32)>>>(Wz, 0);
    k_convert_w<<<dim3(32, 32), dim3(32, 32)>>>(Wh, D_MODEL);

    // 2. fused dual GEMM (fp16 mma.sync, fp32 accumulate, 3-stage pipeline)
    k_gemm<<<dim3(N2 / BN, M / BM), 512, SMEM_TOTAL>>>(bz, bh);

    // 3. chunked scan (sigmoid computed once, in pass 1)
    k_scan1<<<dim3(NCHAN / 256, NCH), 256>>>();
    k_scan2<<<NCHAN / 256, 256>>>();
    k_scan3<<<dim3(NCHAN / 256, NCH), 256>>>(out);
}

// round 4
// speedup vs baseline: 1.2863x; 1.1436x over previous
#include <cuda_runtime.h>
#include <cuda_fp16.h>
#include <cstdint>

// ============================================================================
// Problem dims
// ============================================================================
constexpr int D_MODEL = 1024;
constexpr int BATCH   = 4;
constexpr int SEQ     = 4096;
constexpr int M       = BATCH * SEQ;   // 16384 rows (B*T)
constexpr int K       = D_MODEL;       // 1024
constexpr int N2      = 2 * D_MODEL;   // 2048 interleaved cols (z_d, h_d pairs)

// Scan chunking
constexpr int TC    = 128;             // timesteps per chunk
constexpr int NCH   = SEQ / TC;        // 32 chunks
constexpr int NCHAN = BATCH * D_MODEL; // 4096 channels

// ============================================================================
// Scratch (device globals — no allocation allowed)
// ============================================================================
__device__ __align__(16) __half g_A[(size_t)M * K];       // x fp16   (32 MB)
__device__ __align__(16) __half g_B[(size_t)N2 * K];      // interleaved W^T (4 MB)
__device__ __align__(16) float2 g_ab[(size_t)M * D_MODEL]; // {a=1-s, b=s*htilde} (128 MB)
__device__ float g_cA[NCH * NCHAN];
__device__ float g_cB[NCH * NCHAN];
__device__ float g_carry[NCH * NCHAN];

// ============================================================================
// PTX helpers (sm_100 base-target safe)
// ============================================================================
__device__ __forceinline__ uint32_t smem_u32(const void* p) {
    uint32_t a;
    asm("{ .reg .u64 t; cvta.to.shared.u64 t, %1; cvt.u32.u64 %0, t; }" : "=r"(a) : "l"(p));
    return a;
}
__device__ __forceinline__ void cp_async16(uint32_t s, const void* g) {
    asm volatile("cp.async.cg.shared.global [%0], [%1], 16;" :: "r"(s), "l"(g) : "memory");
}
#define CP_COMMIT() asm volatile("cp.async.commit_group;" ::: "memory")
template <int N>
__device__ __forceinline__ void cp_wait() {
    asm volatile("cp.async.wait_group %0;" :: "n"(N) : "memory");
}
__device__ __forceinline__ void ldsm_x4(uint32_t& r0, uint32_t& r1, uint32_t& r2, uint32_t& r3,
                                        uint32_t s) {
    asm volatile("ldmatrix.sync.aligned.m8n8.x4.shared.b16 {%0,%1,%2,%3}, [%4];"
                 : "=r"(r0), "=r"(r1), "=r"(r2), "=r"(r3) : "r"(s));
}
__device__ __forceinline__ void mma16816(float* c, const uint32_t* a, const uint32_t* b) {
    asm volatile(
        "mma.sync.aligned.m16n8k16.row.col.f32.f16.f16.f32 "
        "{%0,%1,%2,%3}, {%4,%5,%6,%7}, {%8,%9}, {%0,%1,%2,%3};"
        : "+f"(c[0]), "+f"(c[1]), "+f"(c[2]), "+f"(c[3])
        : "r"(a[0]), "r"(a[1]), "r"(a[2]), "r"(a[3]), "r"(b[0]), "r"(b[1]));
}
#define SWZ128(off) ((off) ^ (((off) >> 3) & 0x70))

// sigmoid(z) = 0.5 + 0.5*tanh(z/2)  — single MUFU (tanh.approx)
__device__ __forceinline__ float sigmoid_fast(float z) {
    float t;
    asm("tanh.approx.f32 %0, %1;" : "=f"(t) : "f"(0.5f * z));
    return __fmaf_rn(0.5f, t, 0.5f);
}

// ============================================================================
// Kernel 1: x (fp32) -> fp16
// ============================================================================
__global__ void k_convert_x(const float4* __restrict__ x4) {
    int i = blockIdx.x * blockDim.x + threadIdx.x;
    if (i >= (M * K) / 4) return;
    float4 v = x4[i];
    __half2 h0 = __floats2half2_rn(v.x, v.y);
    __half2 h1 = __floats2half2_rn(v.z, v.w);
    uint2 p;
    p.x = *reinterpret_cast<uint32_t*>(&h0);
    p.y = *reinterpret_cast<uint32_t*>(&h1);
    reinterpret_cast<uint2*>(g_A)[i] = p;
}

// ============================================================================
// Kernel 2: W [K,N] fp32 -> g_B row (2n+which) = W[:,n] fp16 (interleaved z/h)
// ============================================================================
__global__ void k_convert_w(const float* __restrict__ W, int which) {
    __shared__ float t[32][33];
    int tx = threadIdx.x, ty = threadIdx.y;
    int K0 = blockIdx.x * 32, N0 = blockIdx.y * 32;
    t[ty][tx] = W[(size_t)(K0 + ty) * D_MODEL + (N0 + tx)];
    __syncthreads();
    int n = N0 + ty, k = K0 + tx;
    g_B[(size_t)(2 * n + which) * K + k] = __float2half_rn(t[tx][ty]);
}

// ============================================================================
// Kernel 3: GEMM + fused gate epilogue
// pre[M, N2] = A @ B^T + bias (interleaved); writes g_ab = {1-s, s*htilde}
// BM=128, BN=256, BK=64, 256 threads (8 warps, warp tile 64x64), 3-stage
// ============================================================================
constexpr int BM = 128, BN = 256, BK = 64;
constexpr int KT = K / BK;                 // 16 k-chunks
constexpr int SA_BYTES = BM * 128;         // 16 KB
constexpr int SB_BYTES = BN * 128;         // 32 KB
constexpr int STAGE    = SA_BYTES + SB_BYTES;   // 48 KB
constexpr int NSTAGE   = 3;
constexpr int SMEM_TOTAL = NSTAGE * STAGE;      // 144 KB

__global__ void __launch_bounds__(256, 1)
k_gemm(const float* __restrict__ bz, const float* __restrict__ bh) {
    extern __shared__ char smem[];
    uint32_t sbase = smem_u32(smem);
    int tid = threadIdx.x;
    int wid = tid >> 5, lid = tid & 31;
    int n0 = blockIdx.x * BN;   // interleaved col base (0..2048 step 256)
    int m0 = blockIdx.y * BM;
    int wm = wid & 1;           // 2 warp-rows (64 rows each)
    int wn = wid >> 1;          // 4 warp-cols (64 cols each)

    const char* gA = (const char*)g_A + (size_t)m0 * (K * 2);
    const char* gB = (const char*)g_B + (size_t)n0 * (K * 2);

    // per-thread load coords (16B chunks)
    int la_row[4], la_col[4];
    uint32_t la_s[4];
    #pragma unroll
    for (int i = 0; i < 4; i++) {
        int idx = tid + i * 256;
        la_row[i] = idx >> 3; la_col[i] = (idx & 7) * 16;
        la_s[i] = SWZ128((uint32_t)(la_row[i] * 128 + la_col[i]));
    }
    int lb_row[8], lb_col[8];
    uint32_t lb_s[8];
    #pragma unroll
    for (int i = 0; i < 8; i++) {
        int idx = tid + i * 256;
        lb_row[i] = idx >> 3; lb_col[i] = (idx & 7) * 16;
        lb_s[i] = SWZ128((uint32_t)(lb_row[i] * 128 + lb_col[i]));
    }

    auto load_stage = [&](int kt, int buf) {
        uint32_t sA = sbase + buf * STAGE;
        uint32_t sB = sA + SA_BYTES;
        size_t kb = (size_t)kt * (BK * 2);
        #pragma unroll
        for (int i = 0; i < 4; i++)
            cp_async16(sA + la_s[i], gA + (size_t)la_row[i] * (K * 2) + kb + la_col[i]);
        #pragma unroll
        for (int i = 0; i < 8; i++)
            cp_async16(sB + lb_s[i], gB + (size_t)lb_row[i] * (K * 2) + kb + lb_col[i]);
        CP_COMMIT();
    };

    float acc[4][8][4];
    #pragma unroll
    for (int i = 0; i < 4; i++)
        #pragma unroll
        for (int j = 0; j < 8; j++)
            #pragma unroll
            for (int r = 0; r < 4; r++) acc[i][j][r] = 0.0f;

    // ldmatrix lane geometry
    int mat = lid >> 3, r8 = lid & 7;
    int a_row_base = wm * 64 + (mat & 1) * 8 + r8;
    int a_col_base = (mat >> 1) * 16;
    int b_row_base = wn * 64 + (mat >> 1) * 8 + r8;
    int b_col_base = (mat & 1) * 16;

    uint32_t afr[2][4][4], bfr[2][8][2];

    auto load_frags = [&](int ks, int slot, uint32_t sA, uint32_t sB) {
        #pragma unroll
        for (int mf = 0; mf < 4; mf++) {
            uint32_t off = SWZ128((uint32_t)((a_row_base + mf * 16) * 128 +
                                             ks * 32 + a_col_base));
            ldsm_x4(afr[slot][mf][0], afr[slot][mf][1],
                    afr[slot][mf][2], afr[slot][mf][3], sA + off);
        }
        #pragma unroll
        for (int np = 0; np < 4; np++) {
            uint32_t off = SWZ128((uint32_t)((b_row_base + np * 16) * 128 +
                                             ks * 32 + b_col_base));
            uint32_t r0, r1, r2, r3;
            ldsm_x4(r0, r1, r2, r3, sB + off);
            bfr[slot][np * 2 + 0][0] = r0; bfr[slot][np * 2 + 0][1] = r1;
            bfr[slot][np * 2 + 1][0] = r2; bfr[slot][np * 2 + 1][1] = r3;
        }
    };

    // prologue: prefetch 2 stages
    load_stage(0, 0);
    load_stage(1, 1);

    int buf = 0, nbuf = 2;
    for (int kt = 0; kt < KT; kt++) {
        if (kt == KT - 1) cp_wait<0>(); else cp_wait<1>();
        __syncthreads();
        if (kt + 2 < KT) load_stage(kt + 2, nbuf);

        uint32_t sA = sbase + buf * STAGE;
        uint32_t sB = sA + SA_BYTES;

        load_frags(0, 0, sA, sB);
        #pragma unroll
        for (int ks = 0; ks < 4; ks++) {
            if (ks < 3) load_frags(ks + 1, (ks + 1) & 1, sA, sB);
            int sl = ks & 1;
            #pragma unroll
            for (int mf = 0; mf < 4; mf++)
                #pragma unroll
                for (int nf = 0; nf < 8; nf++)
                    mma16816(acc[mf][nf], afr[sl][mf], bfr[sl][nf]);
        }
        buf = (buf == NSTAGE - 1) ? 0 : buf + 1;
        nbuf = (nbuf == NSTAGE - 1) ? 0 : nbuf + 1;
    }

    // ---- Fused epilogue: (z, htilde) col-pair -> {a, b} ----
    // thread holds cols lc (even, = z_d) and lc+1 (odd, = htilde_d)
    int lr = lid >> 2, lq = (lid & 3);
    #pragma unroll
    for (int mf = 0; mf < 4; mf++) {
        int row0 = m0 + wm * 64 + mf * 16 + lr;
        #pragma unroll
        for (int nf = 0; nf < 8; nf++) {
            int col = wn * 64 + nf * 8 + lq * 2;       // even interleaved col
            int d = (n0 + col) >> 1;                   // channel 0..1023
            float bzv = __ldg(bz + d), bhv = __ldg(bh + d);
            float s0 = sigmoid_fast(acc[mf][nf][0] + bzv);
            float s1 = sigmoid_fast(acc[mf][nf][2] + bzv);
            float2 v0 = {1.0f - s0, s0 * (acc[mf][nf][1] + bhv)};
            float2 v1 = {1.0f - s1, s1 * (acc[mf][nf][3] + bhv)};
            g_ab[(size_t)row0 * D_MODEL + d]       = v0;
            g_ab[(size_t)(row0 + 8) * D_MODEL + d] = v1;
        }
    }
}

// ============================================================================
// Scan over h_t = a_t * h_{t-1} + b_t  (a,b precomputed in g_ab)
// ============================================================================
__global__ void k_scan1() {
    int ch = blockIdx.x * blockDim.x + threadIdx.x;   // channel 0..4095
    int chunk = blockIdx.y;
    int b = ch >> 10, d = ch & (D_MODEL - 1);
    const float2* p = g_ab + ((size_t)b * SEQ + (size_t)chunk * TC) * D_MODEL + d;
    float A = 1.0f, Bc = 0.0f;
    #pragma unroll 4
    for (int t = 0; t < TC; t++) {
        float2 v = *p;
        p += D_MODEL;
        A *= v.x;
        Bc = __fmaf_rn(v.x, Bc, v.y);
    }
    g_cA[chunk * NCHAN + ch] = A;
    g_cB[chunk * NCHAN + ch] = Bc;
}

__global__ void k_scan2() {
    int ch = blockIdx.x * blockDim.x + threadIdx.x;
    float h = 0.0f;
    #pragma unroll
    for (int c = 0; c < NCH; c++) {
        g_carry[c * NCHAN + ch] = h;
        h = __fmaf_rn(g_cA[c * NCHAN + ch], h, g_cB[c * NCHAN + ch]);
    }
}

__global__ void k_scan3(float* __restrict__ out) {
    int ch = blockIdx.x * blockDim.x + threadIdx.x;
    int chunk = blockIdx.y;
    int b = ch >> 10, d = ch & (D_MODEL - 1);
    size_t row = (size_t)b * SEQ + (size_t)chunk * TC;
    const float2* p = g_ab + row * D_MODEL + d;
    float* o = out + row * D_MODEL + d;
    float h = g_carry[chunk * NCHAN + ch];
    #pragma unroll 4
    for (int t = 0; t < TC; t++) {
        float2 v = *p;
        p += D_MODEL;
        h = __fmaf_rn(v.x, h, v.y);
        *o = h;
        o += D_MODEL;
    }
}

// ============================================================================
// Launch
// ============================================================================
extern "C" void kernel_launch(void* const* d_in, const int* in_sizes, int n_in,
                              void* d_out, int out_size) {
    const float* x  = (const float*)d_in[0];
    const float* Wz = (const float*)d_in[1];
    const float* bz = (const float*)d_in[2];
    const float* Wh = (const float*)d_in[3];
    const float* bh = (const float*)d_in[4];
    float* out = (float*)d_out;

    cudaFuncSetAttribute(k_gemm, cudaFuncAttributeMaxDynamicSharedMemorySize, SMEM_TOTAL);

    // 1. converts (interleaved weight layout: row 2d = Wz_d, row 2d+1 = Wh_d)
    k_convert_x<<<(M * K / 4 + 255) / 256, 256>>>((const float4*)x);
    k_convert_w<<<dim3(32, 32), dim3(32, 32)>>>(Wz, 0);
    k_convert_w<<<dim3(32, 32), dim3(32, 32)>>>(Wh, 1);

    // 2. GEMM with fused sigmoid/gate epilogue
    k_gemm<<<dim3(N2 / BN, M / BM), 256, SMEM_TOTAL>>>(bz, bh);

    // 3. chunked scan over (a, b)
    k_scan1<<<dim3(NCHAN / 256, NCH), 256>>>();
    k_scan2<<<NCHAN / 256, 256>>>();
    k_scan3<<<dim3(NCHAN / 256, NCH), 256>>>(out);
}